// round 16
// baseline (speedup 1.0000x reference)
#include <cuda_runtime.h>
#include <math.h>

// ---------------------------------------------------------------------------
// GCN forward: 2x GCNConv (deg over dst + self loops, D^-1/2 (A+I) D^-1/2)
// followed by a tiny 3-layer MLP head. N=1e6 nodes, E=16e6 edges.
//
// gcn_conv restructured as:
//   dinv[v] = rsqrt(indeg[v] + 1)
//   g[v]    = (x[v] @ W) * dinv[v]
//   acc[d]  = sum_{edges (s,d)} g[s]            (red.global.add.v4.f32)
//   out[v]  = dinv[v] * (acc[v] + g[v]) + b     (self-loop = g[v] term)
// ---------------------------------------------------------------------------

#define MAXN 1048576   // >= 1,000,000 nodes

__device__ float4 g_g1[MAXN];
__device__ float4 g_acc1[MAXN];
__device__ float4 g_g2[MAXN];
__device__ float4 g_acc2[MAXN];
__device__ float  g_dinv[MAXN];
__device__ int    g_deg[MAXN];

__device__ __forceinline__ void red_add_v4(float4* p, float4 v) {
    asm volatile("red.global.add.v4.f32 [%0], {%1, %2, %3, %4};"
                 :: "l"(p), "f"(v.x), "f"(v.y), "f"(v.z), "f"(v.w)
                 : "memory");
}

// ---- K0: zero degree array -------------------------------------------------
__global__ void k_zero_deg(int n) {
    int v = blockIdx.x * blockDim.x + threadIdx.x;
    if (v < n) g_deg[v] = 0;
}

// ---- K1: count in-degree over dst (vectorized int4, streaming loads) -------
__global__ void k_deg(const int* __restrict__ dst, int E) {
    int i = blockIdx.x * blockDim.x + threadIdx.x;
    int E4 = E >> 2;
    if (i < E4) {
        int4 d = __ldcs(((const int4*)dst) + i);
        atomicAdd(&g_deg[d.x], 1);
        atomicAdd(&g_deg[d.y], 1);
        atomicAdd(&g_deg[d.z], 1);
        atomicAdd(&g_deg[d.w], 1);
    }
    if (i == 0) {
        for (int e = E4 << 2; e < E; e++) atomicAdd(&g_deg[dst[e]], 1);
    }
}

// ---- K2: dinv, g1 = (x @ W1) * dinv, zero acc1 ------------------------------
__global__ void k_node1(const float* __restrict__ x,
                        const float* __restrict__ W1, int n) {
    int v = blockIdx.x * blockDim.x + threadIdx.x;
    if (v >= n) return;
    float di = rsqrtf((float)(g_deg[v] + 1));   // deg >= 1 (self loop)
    g_dinv[v] = di;
    float2 xv = ((const float2*)x)[v];
    // W1: [2,4] row-major
    float w00 = __ldg(&W1[0]), w01 = __ldg(&W1[1]), w02 = __ldg(&W1[2]), w03 = __ldg(&W1[3]);
    float w10 = __ldg(&W1[4]), w11 = __ldg(&W1[5]), w12 = __ldg(&W1[6]), w13 = __ldg(&W1[7]);
    float4 g;
    g.x = fmaf(xv.x, w00, xv.y * w10) * di;
    g.y = fmaf(xv.x, w01, xv.y * w11) * di;
    g.z = fmaf(xv.x, w02, xv.y * w12) * di;
    g.w = fmaf(xv.x, w03, xv.y * w13) * di;
    g_g1[v] = g;
    g_acc1[v] = make_float4(0.f, 0.f, 0.f, 0.f);
}

// ---- K3: scatter layer 1: acc1[dst] += g1[src] ------------------------------
__global__ void k_scat1(const int* __restrict__ src,
                        const int* __restrict__ dst, int E) {
    int i = blockIdx.x * blockDim.x + threadIdx.x;
    int E4 = E >> 2;
    if (i < E4) {
        int4 s = __ldcs(((const int4*)src) + i);
        int4 d = __ldcs(((const int4*)dst) + i);
        float4 a = g_g1[s.x];
        float4 b = g_g1[s.y];
        float4 c = g_g1[s.z];
        float4 e = g_g1[s.w];
        red_add_v4(&g_acc1[d.x], a);
        red_add_v4(&g_acc1[d.y], b);
        red_add_v4(&g_acc1[d.z], c);
        red_add_v4(&g_acc1[d.w], e);
    }
    if (i == 0) {
        for (int e = E4 << 2; e < E; e++) red_add_v4(&g_acc1[dst[e]], g_g1[src[e]]);
    }
}

// ---- K4: h1 = relu(dinv*(acc1+g1)+b1); g2 = (h1@W2)*dinv; zero acc2 ---------
__global__ void k_node2(const float* __restrict__ W2,
                        const float* __restrict__ b1, int n) {
    int v = blockIdx.x * blockDim.x + threadIdx.x;
    if (v >= n) return;
    float di = g_dinv[v];
    float4 a = g_acc1[v];
    float4 g = g_g1[v];
    float h0 = fmaxf(fmaf(di, a.x + g.x, __ldg(&b1[0])), 0.f);
    float h1 = fmaxf(fmaf(di, a.y + g.y, __ldg(&b1[1])), 0.f);
    float h2 = fmaxf(fmaf(di, a.z + g.z, __ldg(&b1[2])), 0.f);
    float h3 = fmaxf(fmaf(di, a.w + g.w, __ldg(&b1[3])), 0.f);
    // W2: [4,3] row-major
    float4 o;
    o.x = (fmaf(h0, __ldg(&W2[0]), fmaf(h1, __ldg(&W2[3]),
           fmaf(h2, __ldg(&W2[6]), h3 * __ldg(&W2[9]))))) * di;
    o.y = (fmaf(h0, __ldg(&W2[1]), fmaf(h1, __ldg(&W2[4]),
           fmaf(h2, __ldg(&W2[7]), h3 * __ldg(&W2[10]))))) * di;
    o.z = (fmaf(h0, __ldg(&W2[2]), fmaf(h1, __ldg(&W2[5]),
           fmaf(h2, __ldg(&W2[8]), h3 * __ldg(&W2[11]))))) * di;
    o.w = 0.f;
    g_g2[v] = o;
    g_acc2[v] = make_float4(0.f, 0.f, 0.f, 0.f);
}

// ---- K5: scatter layer 2: acc2[dst] += g2[src] ------------------------------
__global__ void k_scat2(const int* __restrict__ src,
                        const int* __restrict__ dst, int E) {
    int i = blockIdx.x * blockDim.x + threadIdx.x;
    int E4 = E >> 2;
    if (i < E4) {
        int4 s = __ldcs(((const int4*)src) + i);
        int4 d = __ldcs(((const int4*)dst) + i);
        float4 a = g_g2[s.x];
        float4 b = g_g2[s.y];
        float4 c = g_g2[s.z];
        float4 e = g_g2[s.w];
        red_add_v4(&g_acc2[d.x], a);
        red_add_v4(&g_acc2[d.y], b);
        red_add_v4(&g_acc2[d.z], c);
        red_add_v4(&g_acc2[d.w], e);
    }
    if (i == 0) {
        for (int e = E4 << 2; e < E; e++) red_add_v4(&g_acc2[dst[e]], g_g2[src[e]]);
    }
}

// ---- K6: h2 = sigmoid(dinv*(acc2+g2)+b2); MLP head -> out -------------------
__global__ void k_node3(const float* __restrict__ b2,
                        const float* __restrict__ W3, const float* __restrict__ b3,
                        const float* __restrict__ W4, const float* __restrict__ b4,
                        const float* __restrict__ W5, const float* __restrict__ b5,
                        float* __restrict__ out, int n) {
    int v = blockIdx.x * blockDim.x + threadIdx.x;
    if (v >= n) return;
    float di = g_dinv[v];
    float4 a = g_acc2[v];
    float4 g = g_g2[v];
    float s0 = fmaf(di, a.x + g.x, __ldg(&b2[0]));
    float s1 = fmaf(di, a.y + g.y, __ldg(&b2[1]));
    float s2 = fmaf(di, a.z + g.z, __ldg(&b2[2]));
    float h0 = 1.f / (1.f + expf(-s0));
    float h1 = 1.f / (1.f + expf(-s1));
    float h2 = 1.f / (1.f + expf(-s2));
    // W3: [3,4]
    float t[4];
#pragma unroll
    for (int j = 0; j < 4; j++) {
        float tj = fmaf(h0, __ldg(&W3[0 * 4 + j]),
                   fmaf(h1, __ldg(&W3[1 * 4 + j]),
                   fmaf(h2, __ldg(&W3[2 * 4 + j]), __ldg(&b3[j]))));
        t[j] = fmaxf(tj, 0.f);
    }
    // W4: [4,3]
    float u[3];
#pragma unroll
    for (int j = 0; j < 3; j++) {
        float uj = fmaf(t[0], __ldg(&W4[0 * 3 + j]),
                   fmaf(t[1], __ldg(&W4[1 * 3 + j]),
                   fmaf(t[2], __ldg(&W4[2 * 3 + j]),
                   fmaf(t[3], __ldg(&W4[3 * 3 + j]), __ldg(&b4[j])))));
        u[j] = fmaxf(uj, 0.f);
    }
    // W5: [3,1]
    out[v] = fmaf(u[0], __ldg(&W5[0]),
             fmaf(u[1], __ldg(&W5[1]),
             fmaf(u[2], __ldg(&W5[2]), __ldg(&b5[0]))));
}

// ---------------------------------------------------------------------------
extern "C" void kernel_launch(void* const* d_in, const int* in_sizes, int n_in,
                              void* d_out, int out_size) {
    const float* x   = (const float*)d_in[0];   // [n, 2]
    const int*   ei  = (const int*)  d_in[1];   // [2, E]
    const float* W1  = (const float*)d_in[2];
    const float* b1  = (const float*)d_in[3];
    const float* W2  = (const float*)d_in[4];
    const float* b2  = (const float*)d_in[5];
    const float* W3  = (const float*)d_in[6];
    const float* b3  = (const float*)d_in[7];
    const float* W4  = (const float*)d_in[8];
    const float* b4  = (const float*)d_in[9];
    const float* W5  = (const float*)d_in[10];
    const float* b5  = (const float*)d_in[11];
    float* out = (float*)d_out;

    const int n = in_sizes[0] / 2;      // x has n*2 elements
    const int E = in_sizes[1] / 2;      // edge_index has 2*E elements
    const int* src = ei;
    const int* dst = ei + E;

    const int TB = 256;
    const int nodeBlocks = (n + TB - 1) / TB;
    const int E4 = E >> 2;
    const int edgeBlocks = (E4 + TB - 1) / TB;

    k_zero_deg<<<nodeBlocks, TB>>>(n);
    k_deg    <<<edgeBlocks, TB>>>(dst, E);
    k_node1  <<<nodeBlocks, TB>>>(x, W1, n);
    k_scat1  <<<edgeBlocks, TB>>>(src, dst, E);
    k_node2  <<<nodeBlocks, TB>>>(W2, b1, n);
    k_scat2  <<<edgeBlocks, TB>>>(src, dst, E);
    k_node3  <<<nodeBlocks, TB>>>(b2, W3, b3, W4, b4, W5, b5, out, n);
}

// round 17
// speedup vs baseline: 1.0170x; 1.0170x over previous
#include <cuda_runtime.h>
#include <math.h>

// ---------------------------------------------------------------------------
// GCN forward: 2x GCNConv + tiny MLP head. N=1e6 nodes, E=16e6 edges.
//
// Layer 1 restructured using linearity of the transform:
//   dinv[v]  = rsqrt(indeg[v] + 1)
//   y1[v]    = x[v] * dinv[v]                          (float2!)
//   accY[d] += y1[s]   over edges                      (red.global.add.v2.f32)
//   h1[v]    = relu( dinv[v]*(accY[v] + y1[v]) @ W1 + b1 )   (self loop = y1[v])
// Layer 2 (nonlinear input, 3-dim payload kept as float4):
//   g2[v]    = (h1[v] @ W2) * dinv[v]
//   acc2[d] += g2[s]                                   (red.global.add.v4.f32)
//   h2[v]    = sigmoid( dinv[v]*(acc2[v] + g2[v]) + b2 )
// ---------------------------------------------------------------------------

#define MAXN 1048576   // >= 1,000,000 nodes

__device__ float2 g_y1[MAXN];     // x * dinv  (8B payload for layer-1 scatter)
__device__ float2 g_accY[MAXN];
__device__ float4 g_g2[MAXN];
__device__ float4 g_acc2[MAXN];
__device__ float  g_dinv[MAXN];
__device__ int    g_deg[MAXN];

__device__ __forceinline__ void red_add_v2(float2* p, float2 v) {
    asm volatile("red.global.add.v2.f32 [%0], {%1, %2};"
                 :: "l"(p), "f"(v.x), "f"(v.y)
                 : "memory");
}
__device__ __forceinline__ void red_add_v4(float4* p, float4 v) {
    asm volatile("red.global.add.v4.f32 [%0], {%1, %2, %3, %4};"
                 :: "l"(p), "f"(v.x), "f"(v.y), "f"(v.z), "f"(v.w)
                 : "memory");
}

// ---- K0: zero degree array -------------------------------------------------
__global__ void k_zero_deg(int n) {
    int v = blockIdx.x * blockDim.x + threadIdx.x;
    if (v < n) g_deg[v] = 0;
}

// ---- K1: count in-degree over dst (int4 streaming loads) --------------------
__global__ void k_deg(const int* __restrict__ dst, int E) {
    int i = blockIdx.x * blockDim.x + threadIdx.x;
    int E4 = E >> 2;
    if (i < E4) {
        int4 d = __ldcs(((const int4*)dst) + i);
        atomicAdd(&g_deg[d.x], 1);
        atomicAdd(&g_deg[d.y], 1);
        atomicAdd(&g_deg[d.z], 1);
        atomicAdd(&g_deg[d.w], 1);
    }
    if (i == 0) {
        for (int e = E4 << 2; e < E; e++) atomicAdd(&g_deg[dst[e]], 1);
    }
}

// ---- K2: dinv, y1 = x * dinv, zero accY + acc2 ------------------------------
__global__ void k_node1(const float* __restrict__ x, int n) {
    int v = blockIdx.x * blockDim.x + threadIdx.x;
    if (v >= n) return;
    float di = rsqrtf((float)(g_deg[v] + 1));   // deg >= 1 (self loop)
    g_dinv[v] = di;
    float2 xv = ((const float2*)x)[v];
    g_y1[v]  = make_float2(xv.x * di, xv.y * di);
    g_accY[v] = make_float2(0.f, 0.f);
    g_acc2[v] = make_float4(0.f, 0.f, 0.f, 0.f);
}

// ---- K3: scatter layer 1: accY[dst] += y1[src]  (8B payload) ----------------
__global__ void k_scat1(const int* __restrict__ src,
                        const int* __restrict__ dst, int E) {
    int i = blockIdx.x * blockDim.x + threadIdx.x;
    int E4 = E >> 2;
    if (i < E4) {
        int4 s = __ldcs(((const int4*)src) + i);
        int4 d = __ldcs(((const int4*)dst) + i);
        float2 a = g_y1[s.x];
        float2 b = g_y1[s.y];
        float2 c = g_y1[s.z];
        float2 e = g_y1[s.w];
        red_add_v2(&g_accY[d.x], a);
        red_add_v2(&g_accY[d.y], b);
        red_add_v2(&g_accY[d.z], c);
        red_add_v2(&g_accY[d.w], e);
    }
    if (i == 0) {
        for (int e = E4 << 2; e < E; e++) red_add_v2(&g_accY[dst[e]], g_y1[src[e]]);
    }
}

// ---- K4: h1 = relu(dinv*(accY+y1)@W1 + b1); g2 = (h1@W2)*dinv ---------------
__global__ void k_node2(const float* __restrict__ W1, const float* __restrict__ b1,
                        const float* __restrict__ W2, int n) {
    int v = blockIdx.x * blockDim.x + threadIdx.x;
    if (v >= n) return;
    float di = g_dinv[v];
    float2 a = g_accY[v];
    float2 y = g_y1[v];
    float z0 = di * (a.x + y.x);
    float z1 = di * (a.y + y.y);
    // W1: [2,4] row-major
    float h0 = fmaxf(fmaf(z0, __ldg(&W1[0]), fmaf(z1, __ldg(&W1[4]), __ldg(&b1[0]))), 0.f);
    float h1 = fmaxf(fmaf(z0, __ldg(&W1[1]), fmaf(z1, __ldg(&W1[5]), __ldg(&b1[1]))), 0.f);
    float h2 = fmaxf(fmaf(z0, __ldg(&W1[2]), fmaf(z1, __ldg(&W1[6]), __ldg(&b1[2]))), 0.f);
    float h3 = fmaxf(fmaf(z0, __ldg(&W1[3]), fmaf(z1, __ldg(&W1[7]), __ldg(&b1[3]))), 0.f);
    // W2: [4,3] row-major
    float4 o;
    o.x = (fmaf(h0, __ldg(&W2[0]), fmaf(h1, __ldg(&W2[3]),
           fmaf(h2, __ldg(&W2[6]), h3 * __ldg(&W2[9]))))) * di;
    o.y = (fmaf(h0, __ldg(&W2[1]), fmaf(h1, __ldg(&W2[4]),
           fmaf(h2, __ldg(&W2[7]), h3 * __ldg(&W2[10]))))) * di;
    o.z = (fmaf(h0, __ldg(&W2[2]), fmaf(h1, __ldg(&W2[5]),
           fmaf(h2, __ldg(&W2[8]), h3 * __ldg(&W2[11]))))) * di;
    o.w = 0.f;
    g_g2[v] = o;
}

// ---- K5: scatter layer 2: acc2[dst] += g2[src] ------------------------------
__global__ void k_scat2(const int* __restrict__ src,
                        const int* __restrict__ dst, int E) {
    int i = blockIdx.x * blockDim.x + threadIdx.x;
    int E4 = E >> 2;
    if (i < E4) {
        int4 s = __ldcs(((const int4*)src) + i);
        int4 d = __ldcs(((const int4*)dst) + i);
        float4 a = g_g2[s.x];
        float4 b = g_g2[s.y];
        float4 c = g_g2[s.z];
        float4 e = g_g2[s.w];
        red_add_v4(&g_acc2[d.x], a);
        red_add_v4(&g_acc2[d.y], b);
        red_add_v4(&g_acc2[d.z], c);
        red_add_v4(&g_acc2[d.w], e);
    }
    if (i == 0) {
        for (int e = E4 << 2; e < E; e++) red_add_v4(&g_acc2[dst[e]], g_g2[src[e]]);
    }
}

// ---- K6: h2 = sigmoid(dinv*(acc2+g2)+b2); MLP head -> out -------------------
__global__ void k_node3(const float* __restrict__ b2,
                        const float* __restrict__ W3, const float* __restrict__ b3,
                        const float* __restrict__ W4, const float* __restrict__ b4,
                        const float* __restrict__ W5, const float* __restrict__ b5,
                        float* __restrict__ out, int n) {
    int v = blockIdx.x * blockDim.x + threadIdx.x;
    if (v >= n) return;
    float di = g_dinv[v];
    float4 a = g_acc2[v];
    float4 g = g_g2[v];
    float s0 = fmaf(di, a.x + g.x, __ldg(&b2[0]));
    float s1 = fmaf(di, a.y + g.y, __ldg(&b2[1]));
    float s2 = fmaf(di, a.z + g.z, __ldg(&b2[2]));
    float h0 = 1.f / (1.f + expf(-s0));
    float h1 = 1.f / (1.f + expf(-s1));
    float h2 = 1.f / (1.f + expf(-s2));
    // W3: [3,4]
    float t[4];
#pragma unroll
    for (int j = 0; j < 4; j++) {
        float tj = fmaf(h0, __ldg(&W3[0 * 4 + j]),
                   fmaf(h1, __ldg(&W3[1 * 4 + j]),
                   fmaf(h2, __ldg(&W3[2 * 4 + j]), __ldg(&b3[j]))));
        t[j] = fmaxf(tj, 0.f);
    }
    // W4: [4,3]
    float u[3];
#pragma unroll
    for (int j = 0; j < 3; j++) {
        float uj = fmaf(t[0], __ldg(&W4[0 * 3 + j]),
                   fmaf(t[1], __ldg(&W4[1 * 3 + j]),
                   fmaf(t[2], __ldg(&W4[2 * 3 + j]),
                   fmaf(t[3], __ldg(&W4[3 * 3 + j]), __ldg(&b4[j])))));
        u[j] = fmaxf(uj, 0.f);
    }
    // W5: [3,1]
    out[v] = fmaf(u[0], __ldg(&W5[0]),
             fmaf(u[1], __ldg(&W5[1]),
             fmaf(u[2], __ldg(&W5[2]), __ldg(&b5[0]))));
}

// ---------------------------------------------------------------------------
extern "C" void kernel_launch(void* const* d_in, const int* in_sizes, int n_in,
                              void* d_out, int out_size) {
    const float* x   = (const float*)d_in[0];   // [n, 2]
    const int*   ei  = (const int*)  d_in[1];   // [2, E]
    const float* W1  = (const float*)d_in[2];
    const float* b1  = (const float*)d_in[3];
    const float* W2  = (const float*)d_in[4];
    const float* b2  = (const float*)d_in[5];
    const float* W3  = (const float*)d_in[6];
    const float* b3  = (const float*)d_in[7];
    const float* W4  = (const float*)d_in[8];
    const float* b4  = (const float*)d_in[9];
    const float* W5  = (const float*)d_in[10];
    const float* b5  = (const float*)d_in[11];
    float* out = (float*)d_out;

    const int n = in_sizes[0] / 2;      // x has n*2 elements
    const int E = in_sizes[1] / 2;      // edge_index has 2*E elements
    const int* src = ei;
    const int* dst = ei + E;

    const int TB = 256;
    const int nodeBlocks = (n + TB - 1) / TB;
    const int E4 = E >> 2;
    const int edgeBlocks = (E4 + TB - 1) / TB;

    k_zero_deg<<<nodeBlocks, TB>>>(n);
    k_deg    <<<edgeBlocks, TB>>>(dst, E);
    k_node1  <<<nodeBlocks, TB>>>(x, n);
    k_scat1  <<<edgeBlocks, TB>>>(src, dst, E);
    k_node2  <<<nodeBlocks, TB>>>(W1, b1, W2, n);
    k_scat2  <<<edgeBlocks, TB>>>(src, dst, E);
    k_node3  <<<nodeBlocks, TB>>>(b2, W3, b3, W4, b4, W5, b5, out, n);
}